// round 3
// baseline (speedup 1.0000x reference)
#include <cuda_runtime.h>
#include <cuda_bf16.h>
#include <cstdint>
#include <math.h>

#define HD 1024
#define NS 65536
#define BS 2048
#define TOPK 8
#define MCAND 32

// ---------------- device scratch (static, allocation-free) ----------------
__device__ float         g_colmax[HD];
__device__ float         g_scale[HD];
__device__ float         g_invn[NS];
__device__ __nv_bfloat16 g_an_bf[(size_t)NS * HD];     // 128 MB bf16 normalized addresses
__device__ float         g_query[(size_t)BS * HD];
__device__ float         g_qn[(size_t)BS * HD];
__device__ __nv_bfloat16 g_qn_bf[(size_t)BS * HD];
__device__ float         g_scores[(size_t)BS * NS];    // 512 MB approx scores
__device__ int           g_cand[BS * MCAND];
__device__ float         g_read[(size_t)BS * HD];

// ---------------- per-column |max| of contents -> int8 scale ----------------
__global__ void k_zero_colmax() { g_colmax[threadIdx.x] = 0.f; }

__global__ void k_colmax(const float* __restrict__ contents) {
    int col = blockIdx.x * 256 + threadIdx.x;
    int r0  = blockIdx.y * 256;
    float m = 0.f;
    for (int r = 0; r < 256; r++)
        m = fmaxf(m, fabsf(contents[(size_t)(r0 + r) * HD + col]));
    atomicMax((int*)&g_colmax[col], __float_as_int(m));  // valid: values >= 0
}

__global__ void k_scale() {
    int h = threadIdx.x;
    g_scale[h] = fmaxf(g_colmax[h] / 127.0f, 1e-6f);
}

// ---------------- address row norms + bf16 normalized copy ----------------
__global__ void __launch_bounds__(256) k_addrnorm(const float* __restrict__ addresses) {
    __shared__ float red[256];
    __shared__ float s_inv;
    int row = blockIdx.x, t = threadIdx.x;
    float v[4]; float ss = 0.f;
#pragma unroll
    for (int i = 0; i < 4; i++) {
        v[i] = addresses[(size_t)row * HD + t + i * 256];
        ss += v[i] * v[i];
    }
    red[t] = ss; __syncthreads();
    for (int s = 128; s > 0; s >>= 1) { if (t < s) red[t] += red[t + s]; __syncthreads(); }
    if (t == 0) {
        float n = fmaxf(sqrtf(red[0]), 1e-8f);
        s_inv = 1.0f / n;
        g_invn[row] = s_inv;
    }
    __syncthreads();
    float inv = s_inv;
#pragma unroll
    for (int i = 0; i < 4; i++)
        g_an_bf[(size_t)row * HD + t + i * 256] = __float2bfloat16(v[i] * inv);
}

// ---------------- query row norms: fp32 (division, matches jax) + bf16 ----------------
__global__ void __launch_bounds__(256) k_qnorm() {
    __shared__ float red[256];
    __shared__ float s_n;
    int row = blockIdx.x, t = threadIdx.x;
    float v[4]; float ss = 0.f;
#pragma unroll
    for (int i = 0; i < 4; i++) {
        v[i] = g_query[(size_t)row * HD + t + i * 256];
        ss += v[i] * v[i];
    }
    red[t] = ss; __syncthreads();
    for (int s = 128; s > 0; s >>= 1) { if (t < s) red[t] += red[t + s]; __syncthreads(); }
    if (t == 0) s_n = fmaxf(sqrtf(red[0]), 1e-8f);
    __syncthreads();
    float n = s_n;
#pragma unroll
    for (int i = 0; i < 4; i++) {
        float qv = v[i] / n;                 // division: match reference rounding
        g_qn[(size_t)row * HD + t + i * 256]    = qv;
        g_qn_bf[(size_t)row * HD + t + i * 256] = __float2bfloat16(qv);
    }
}

// ---------------- fp32 tiled GEMM: C[m][n] = sum_k A[m][k] * B[n][k] ----------------
// M=2048 (grid.y*64), N=1024 (grid.x*64), K=1024. 256 threads, 4x4 microtile.
__device__ __forceinline__ void gemm_body(const float* __restrict__ A,
                                          const float* __restrict__ B,
                                          float* __restrict__ C,
                                          int Nn, int Kk) {
    __shared__ float sA[16][68];   // [k][m], padded for .128 alignment
    __shared__ float sB[16][68];   // [k][n]
    const int tid = threadIdx.x;
    const int tx = tid % 16, ty = tid / 16;
    const int bm = blockIdx.y * 64, bn = blockIdx.x * 64;
    const int tk = tid % 16, tr = tid / 16;
    float acc[4][4];
#pragma unroll
    for (int i = 0; i < 4; i++)
#pragma unroll
        for (int j = 0; j < 4; j++) acc[i][j] = 0.f;

    for (int k0 = 0; k0 < Kk; k0 += 16) {
#pragma unroll
        for (int i = 0; i < 4; i++) {
            sA[tk][tr + i * 16] = A[(size_t)(bm + tr + i * 16) * Kk + k0 + tk];
            sB[tk][tr + i * 16] = B[(size_t)(bn + tr + i * 16) * Kk + k0 + tk];
        }
        __syncthreads();
#pragma unroll
        for (int kk = 0; kk < 16; kk++) {
            float4 a = *(const float4*)&sA[kk][ty * 4];
            float4 b = *(const float4*)&sB[kk][tx * 4];
            acc[0][0] += a.x * b.x; acc[0][1] += a.x * b.y; acc[0][2] += a.x * b.z; acc[0][3] += a.x * b.w;
            acc[1][0] += a.y * b.x; acc[1][1] += a.y * b.y; acc[1][2] += a.y * b.z; acc[1][3] += a.y * b.w;
            acc[2][0] += a.z * b.x; acc[2][1] += a.z * b.y; acc[2][2] += a.z * b.z; acc[2][3] += a.z * b.w;
            acc[3][0] += a.w * b.x; acc[3][1] += a.w * b.y; acc[3][2] += a.w * b.z; acc[3][3] += a.w * b.w;
        }
        __syncthreads();
    }
#pragma unroll
    for (int i = 0; i < 4; i++) {
        float4 o = make_float4(acc[i][0], acc[i][1], acc[i][2], acc[i][3]);
        *(float4*)&C[(size_t)(bm + ty * 4 + i) * Nn + bn + tx * 4] = o;
    }
}

__global__ void __launch_bounds__(256) k_gemm_query(const float* __restrict__ x,
                                                    const float* __restrict__ W) {
    gemm_body(x, W, g_query, HD, HD);
}
__global__ void __launch_bounds__(256) k_gemm_out(const float* __restrict__ W,
                                                  float* __restrict__ out) {
    gemm_body(g_read, W, out, HD, HD);
}

// ---------------- bf16 tensor-core scores: g_scores = g_qn_bf @ g_an_bf^T ----------------
// block: 256 thr = 8 warps (2x4), BM=64 BN=128 BK=32; warp tile 32x32 via m16n8k16.
__global__ void __launch_bounds__(256) k_scores_mma() {
    __shared__ __nv_bfloat16 sA[64][34];    // pad -> word stride 17 (conflict-free frag loads)
    __shared__ __nv_bfloat16 sB[128][34];
    const int tid = threadIdx.x;
    const int warp = tid / 32, lane = tid % 32;
    const int wm = warp / 4, wn = warp % 4;
    const int m0 = blockIdx.y * 64, n0 = blockIdx.x * 128;
    const int g = lane >> 2, tg = lane & 3;

    float acc[2][4][4];
#pragma unroll
    for (int mi = 0; mi < 2; mi++)
#pragma unroll
        for (int ni = 0; ni < 4; ni++)
#pragma unroll
            for (int r = 0; r < 4; r++) acc[mi][ni][r] = 0.f;

    const uint32_t* Ag = (const uint32_t*)g_qn_bf;   // 512 uints per row
    const uint32_t* Bg = (const uint32_t*)g_an_bf;

    for (int k0 = 0; k0 < HD; k0 += 32) {
#pragma unroll
        for (int i = 0; i < 4; i++) {               // A tile: 64 x 32 bf16 = 1024 uints
            int idx = tid + i * 256;
            int r = idx >> 4, w = idx & 15;
            uint32_t v = Ag[(size_t)(m0 + r) * (HD / 2) + (k0 >> 1) + w];
            *(uint32_t*)&sA[r][w * 2] = v;
        }
#pragma unroll
        for (int i = 0; i < 8; i++) {               // B tile: 128 x 32 bf16 = 2048 uints
            int idx = tid + i * 256;
            int r = idx >> 4, w = idx & 15;
            uint32_t v = Bg[(size_t)(n0 + r) * (HD / 2) + (k0 >> 1) + w];
            *(uint32_t*)&sB[r][w * 2] = v;
        }
        __syncthreads();

        const uint32_t* baseA = (const uint32_t*)&sA[0][0];
        const uint32_t* baseB = (const uint32_t*)&sB[0][0];
#pragma unroll
        for (int ks = 0; ks < 2; ks++) {
            const int kw = ks * 8;                  // k offset in words (16 bf16)
            uint32_t afr[2][4];
#pragma unroll
            for (int mi = 0; mi < 2; mi++) {
                int row = wm * 32 + mi * 16 + g;
                int w0 = row * 17 + kw + tg;
                afr[mi][0] = baseA[w0];
                afr[mi][1] = baseA[w0 + 8 * 17];
                afr[mi][2] = baseA[w0 + 4];
                afr[mi][3] = baseA[w0 + 8 * 17 + 4];
            }
            uint32_t bfr[4][2];
#pragma unroll
            for (int ni = 0; ni < 4; ni++) {
                int n = wn * 32 + ni * 8 + g;
                int w0 = n * 17 + kw + tg;
                bfr[ni][0] = baseB[w0];
                bfr[ni][1] = baseB[w0 + 4];
            }
#pragma unroll
            for (int mi = 0; mi < 2; mi++)
#pragma unroll
                for (int ni = 0; ni < 4; ni++) {
                    asm volatile(
                        "mma.sync.aligned.m16n8k16.row.col.f32.bf16.bf16.f32 "
                        "{%0,%1,%2,%3}, {%4,%5,%6,%7}, {%8,%9}, {%0,%1,%2,%3};"
                        : "+f"(acc[mi][ni][0]), "+f"(acc[mi][ni][1]),
                          "+f"(acc[mi][ni][2]), "+f"(acc[mi][ni][3])
                        : "r"(afr[mi][0]), "r"(afr[mi][1]), "r"(afr[mi][2]), "r"(afr[mi][3]),
                          "r"(bfr[ni][0]), "r"(bfr[ni][1]));
                }
        }
        __syncthreads();
    }
#pragma unroll
    for (int mi = 0; mi < 2; mi++)
#pragma unroll
        for (int ni = 0; ni < 4; ni++) {
            int row = m0 + wm * 32 + mi * 16 + g;
            int col = n0 + wn * 32 + ni * 8 + tg * 2;
            *(float2*)&g_scores[(size_t)row * NS + col] =
                make_float2(acc[mi][ni][0], acc[mi][ni][1]);
            *(float2*)&g_scores[(size_t)(row + 8) * NS + col] =
                make_float2(acc[mi][ni][2], acc[mi][ni][3]);
        }
}

// ---------------- top-32 candidate selection per query ----------------
__global__ void __launch_bounds__(256) k_topm() {
    __shared__ float sval[2048];
    __shared__ int   sidx[2048];
    __shared__ float rv[256];
    __shared__ int   rp[256];
    const int q = blockIdx.x, t = threadIdx.x;
    const float* row = g_scores + (size_t)q * NS;

    float tv[8]; int ti[8];
#pragma unroll
    for (int j = 0; j < 8; j++) { tv[j] = -1e30f; ti[j] = 0; }

    for (int i = 0; i < NS / 256; i++) {
        int n = t + i * 256;
        float v = row[n];
        if (v > tv[7]) {
            tv[7] = v; ti[7] = n;
#pragma unroll
            for (int j = 7; j > 0; j--) {
                if (tv[j] > tv[j - 1]) {
                    float fv = tv[j]; tv[j] = tv[j - 1]; tv[j - 1] = fv;
                    int   fi = ti[j]; ti[j] = ti[j - 1]; ti[j - 1] = fi;
                }
            }
        }
    }
#pragma unroll
    for (int j = 0; j < 8; j++) { sval[t * 8 + j] = tv[j]; sidx[t * 8 + j] = ti[j]; }
    __syncthreads();

    for (int r = 0; r < MCAND; r++) {
        float bv = -1e30f; int bp = 0;
#pragma unroll
        for (int j = 0; j < 8; j++) {
            float v = sval[t * 8 + j];
            if (v > bv) { bv = v; bp = t * 8 + j; }
        }
        rv[t] = bv; rp[t] = bp;
        __syncthreads();
        for (int s = 128; s > 0; s >>= 1) {
            if (t < s && rv[t + s] > rv[t]) { rv[t] = rv[t + s]; rp[t] = rp[t + s]; }
            __syncthreads();
        }
        if (t == 0) { g_cand[q * MCAND + r] = sidx[rp[0]]; sval[rp[0]] = -1e30f; }
        __syncthreads();
    }
}

// ---------------- exact fp32 rescore + top-8 + softmax + dequant gather ----------------
__global__ void __launch_bounds__(256) k_rescore(const float* __restrict__ addresses,
                                                 const float* __restrict__ contents) {
    __shared__ float qrow[HD];
    __shared__ float red[256];
    __shared__ float cs[MCAND];
    __shared__ float w8[TOPK];
    __shared__ int   i8[TOPK];
    const int q = blockIdx.x, t = threadIdx.x;

#pragma unroll
    for (int i = 0; i < 4; i++) qrow[t + i * 256] = g_qn[(size_t)q * HD + t + i * 256];
    __syncthreads();

    for (int c = 0; c < MCAND; c++) {
        int idx = g_cand[q * MCAND + c];
        const float* arow = addresses + (size_t)idx * HD;
        float p = 0.f;
#pragma unroll
        for (int i = 0; i < 4; i++) { int h = t + i * 256; p += qrow[h] * arow[h]; }
        red[t] = p; __syncthreads();
        for (int s = 128; s > 0; s >>= 1) { if (t < s) red[t] += red[t + s]; __syncthreads(); }
        if (t == 0) cs[c] = red[0] * g_invn[idx];
        __syncthreads();
    }

    if (t == 0) {
        float kv[TOPK];
        for (int j = 0; j < TOPK; j++) {
            float bv = -1e30f; int bc = 0;
            for (int c = 0; c < MCAND; c++)
                if (cs[c] > bv) { bv = cs[c]; bc = c; }
            kv[j] = bv; i8[j] = g_cand[q * MCAND + bc]; cs[bc] = -1e30f;
        }
        float mx = kv[0];                     // selected in descending order
        float e[TOPK]; float ssum = 0.f;
        for (int j = 0; j < TOPK; j++) { e[j] = expf(kv[j] - mx); ssum += e[j]; }
        for (int j = 0; j < TOPK; j++) w8[j] = e[j] / ssum;
    }
    __syncthreads();

#pragma unroll
    for (int i = 0; i < 4; i++) {
        int h = t + i * 256;
        float sc = g_scale[h];
        float a = 0.f;
#pragma unroll
        for (int j = 0; j < TOPK; j++) {
            float v = contents[(size_t)i8[j] * HD + h];
            float qq = rintf(v / sc);                       // round half-to-even, like jnp.round
            qq = fminf(fmaxf(qq, -127.f), 127.f);
            a += w8[j] * (qq * sc);
        }
        g_read[(size_t)q * HD + h] = a;
    }
}

// ---------------- launch ----------------
extern "C" void kernel_launch(void* const* d_in, const int* in_sizes, int n_in,
                              void* d_out, int out_size) {
    const float* x         = (const float*)d_in[0];
    const float* addresses = (const float*)d_in[1];
    const float* contents  = (const float*)d_in[2];
    const float* W_addr    = (const float*)d_in[3];
    const float* W_read    = (const float*)d_in[4];
    float* out = (float*)d_out;

    k_zero_colmax<<<1, HD>>>();
    k_colmax<<<dim3(HD / 256, NS / 256), 256>>>(contents);
    k_scale<<<1, HD>>>();
    k_addrnorm<<<NS, 256>>>(addresses);
    k_gemm_query<<<dim3(HD / 64, BS / 64), 256>>>(x, W_addr);
    k_qnorm<<<BS, 256>>>();
    k_scores_mma<<<dim3(NS / 128, BS / 64), 256>>>();
    k_topm<<<BS, 256>>>();
    k_rescore<<<BS, 256>>>(addresses, contents);
    k_gemm_out<<<dim3(HD / 64, BS / 64), 256>>>(W_read, out);
}